// round 13
// baseline (speedup 1.0000x reference)
#include <cuda_runtime.h>
#include <cuda_bf16.h>

// ---------------- problem constants -----------------------------------------
#define N_TOK 8192
#define H_DIM 1024
#define F_DIM 4096
#define E_NUM 8
#define K_CAP 1280   // int(8192 * 1.25 / 8)

// ---------------- scratch: total ~244.6 MB (< proven 252.7 MB budget) -------
__device__ unsigned long long g_keys[E_NUM * N_TOK];     // 512 KB
__device__ unsigned long long g_sort[E_NUM * N_TOK];     // 512 KB
__device__ int   g_indices[E_NUM * K_CAP];               // 40 KB
__device__ int   g_slot[N_TOK * E_NUM];                  // 256 KB
__device__ __nv_bfloat16 xh [(size_t)N_TOK * H_DIM];     // 16.8 MB
__device__ __nv_bfloat16 xl [(size_t)N_TOK * H_DIM];     // 16.8 MB
__device__ __nv_bfloat16 hbh[(size_t)E_NUM * K_CAP * F_DIM];  // 83.9 MB
__device__ __nv_bfloat16 hbl[(size_t)E_NUM * K_CAP * F_DIM];  // 83.9 MB
__device__ float g_eo[(size_t)E_NUM * K_CAP * H_DIM];    // 41.9 MB

// ---------------- helpers -----------------------------------------------------
__device__ __forceinline__ unsigned smem_u32(const void* p) {
    unsigned a;
    asm("{ .reg .u64 t; cvta.to.shared.u64 t, %1; cvt.u32.u64 %0, t; }" : "=r"(a) : "l"(p));
    return a;
}
__device__ __forceinline__ void cp16(unsigned dst, const void* src) {
    asm volatile("cp.async.cg.shared.global [%0], [%1], 16;" :: "r"(dst), "l"(src));
}
__device__ __forceinline__ void ldsm4(unsigned& r0, unsigned& r1, unsigned& r2,
                                      unsigned& r3, unsigned addr) {
    asm volatile("ldmatrix.sync.aligned.m8n8.x4.shared.b16 {%0,%1,%2,%3}, [%4];"
                 : "=r"(r0), "=r"(r1), "=r"(r2), "=r"(r3) : "r"(addr));
}
__device__ __forceinline__ void ldsm4t(unsigned& r0, unsigned& r1, unsigned& r2,
                                       unsigned& r3, unsigned addr) {
    asm volatile("ldmatrix.sync.aligned.m8n8.x4.trans.shared.b16 {%0,%1,%2,%3}, [%4];"
                 : "=r"(r0), "=r"(r1), "=r"(r2), "=r"(r3) : "r"(addr));
}
__device__ __forceinline__ void mma16816(float* c, const unsigned* a, const unsigned* b) {
    asm volatile("mma.sync.aligned.m16n8k16.row.col.f32.bf16.bf16.f32 "
                 "{%0,%1,%2,%3}, {%4,%5,%6,%7}, {%8,%9}, {%0,%1,%2,%3};"
                 : "+f"(c[0]), "+f"(c[1]), "+f"(c[2]), "+f"(c[3])
                 : "r"(a[0]), "r"(a[1]), "r"(a[2]), "r"(a[3]), "r"(b[0]), "r"(b[1]));
}
__device__ __forceinline__ void cvt_split4(float4 v, uint2& hi, uint2& lo) {
    __nv_bfloat162 h01 = __float22bfloat162_rn(make_float2(v.x, v.y));
    __nv_bfloat162 h23 = __float22bfloat162_rn(make_float2(v.z, v.w));
    float2 f01 = __bfloat1622float2(h01);
    float2 f23 = __bfloat1622float2(h23);
    __nv_bfloat162 l01 = __float22bfloat162_rn(make_float2(v.x - f01.x, v.y - f01.y));
    __nv_bfloat162 l23 = __float22bfloat162_rn(make_float2(v.z - f23.x, v.w - f23.y));
    hi.x = *reinterpret_cast<unsigned*>(&h01);
    hi.y = *reinterpret_cast<unsigned*>(&h23);
    lo.x = *reinterpret_cast<unsigned*>(&l01);
    lo.y = *reinterpret_cast<unsigned*>(&l23);
}
__device__ __forceinline__ float silu_f(float v) { return v / (1.0f + expf(-v)); }

// ---------------- gating + x hi/lo split (fused; block = one token) ---------
__global__ void gate_kernel(const float* __restrict__ x,
                            const float* __restrict__ gw) {
    int t = blockIdx.x;
    int tid = threadIdx.x;
    float4 v = *(const float4*)(x + (size_t)t * H_DIM + tid * 4);

    uint2 hh, ll;
    cvt_split4(v, hh, ll);
    *(uint2*)(xh + (size_t)t * H_DIM + tid * 4) = hh;
    *(uint2*)(xl + (size_t)t * H_DIM + tid * 4) = ll;

    double acc[E_NUM];
#pragma unroll
    for (int e = 0; e < E_NUM; ++e) acc[e] = 0.0;
    float vv[4] = {v.x, v.y, v.z, v.w};
#pragma unroll
    for (int r = 0; r < 4; ++r) {
        const float* g = gw + (size_t)(tid * 4 + r) * E_NUM;
#pragma unroll
        for (int e = 0; e < E_NUM; ++e) acc[e] += (double)vv[r] * (double)g[e];
    }
#pragma unroll
    for (int e = 0; e < E_NUM; ++e) {
#pragma unroll
        for (int off = 16; off > 0; off >>= 1)
            acc[e] += __shfl_down_sync(0xffffffffu, acc[e], off);
    }
    __shared__ double red[8][E_NUM];
    int warp = tid >> 5, lane = tid & 31;
    if (lane == 0) {
#pragma unroll
        for (int e = 0; e < E_NUM; ++e) red[warp][e] = acc[e];
    }
    __syncthreads();
    if (tid < E_NUM) {
        double s = 0.0;
        for (int w = 0; w < 8; ++w) s += red[w][tid];
        float lf = (float)s;
        unsigned u = __float_as_uint(lf);
        u = (u & 0x80000000u) ? ~u : (u | 0x80000000u);
        unsigned long long key =
            ((unsigned long long)u << 13) | (unsigned)(8191 - t);
        g_keys[tid * N_TOK + t] = key;
        g_slot[t * E_NUM + tid] = -1;
    }
}

// ---------------- chunk sort: 1024 keys per block, descending ---------------
__global__ void sort_chunk_kernel() {
    __shared__ unsigned long long s[1024];
    int e = blockIdx.y, c = blockIdx.x;
    const unsigned long long* keys = g_keys + e * N_TOK + c * 1024;
    s[threadIdx.x] = ~keys[threadIdx.x];   // ascending of ~k = descending of k
    __syncthreads();
    for (int k = 2; k <= 1024; k <<= 1) {
        for (int j = k >> 1; j > 0; j >>= 1) {
            int i = threadIdx.x, l = i ^ j;
            if (l > i) {
                unsigned long long a = s[i], b = s[l];
                bool up = ((i & k) == 0);
                if (up ? (a > b) : (a < b)) { s[i] = b; s[l] = a; }
            }
            __syncthreads();
        }
    }
    g_sort[e * N_TOK + c * 1024 + threadIdx.x] = ~s[threadIdx.x];
}

// ---------------- 8-way rank merge (exact top-K_CAP) ------------------------
__global__ void merge8_kernel() {
    int e = blockIdx.x;
    const unsigned long long* S = g_sort + e * N_TOK;
    for (int idx = threadIdx.x; idx < N_TOK; idx += 1024) {
        int c = idx >> 10, i = idx & 1023;
        unsigned long long v = S[c * 1024 + i];
        int rank = i;
#pragma unroll
        for (int c2 = 0; c2 < 8; ++c2) {
            if (c2 == c) continue;
            const unsigned long long* o = S + c2 * 1024;
            int lo = 0, hi = 1024;          // count of elements > v (descending)
            while (lo < hi) {
                int mid = (lo + hi) >> 1;
                if (o[mid] > v) lo = mid + 1; else hi = mid;
            }
            rank += lo;
        }
        if (rank < K_CAP) {
            int t = 8191 - (int)(v & 0x1FFFull);
            g_indices[e * K_CAP + rank] = t;
            g_slot[t * E_NUM + e] = rank;
        }
    }
}

// ---------------- HMMA GEMM ---------------------------------------------------
// A (bf16 planes, cp.async): 128 rows x 16k, 64B row stride, unit swz u^(m&3)
// B (fp32 -> reg CVT -> STS): 16 rows x BN, row BROWB bytes, unit swz u^(k&7)
// GEMM1: BN=128, NT=8, occ 2.  GEMM2: BN=64, NT=4, occ 3 (no split-K; more CTAs).
template<bool FIRST>
__global__ __launch_bounds__(128, FIRST ? 2 : 3)
void moe_gemm_kernel(const float* __restrict__ w) {
    constexpr int KTOT = FIRST ? H_DIM : F_DIM;
    constexpr int NEXP = FIRST ? F_DIM : H_DIM;
    constexpr int BN   = FIRST ? 128 : 64;
    constexpr int NT   = FIRST ? 8 : 4;
    constexpr int NCH  = KTOT / 16;
    constexpr unsigned AH = 0, AL = 8192;
    constexpr unsigned BROWB = FIRST ? 256u : 128u;
    constexpr unsigned BH = 16384u;
    constexpr unsigned BL = BH + 16u * BROWB;
    constexpr unsigned STRIDE = BL + 16u * BROWB;   // 24576 / 20480

    __shared__ __align__(1024) unsigned char buf[2][STRIDE];

    const int tid  = threadIdx.x;
    const int wid  = tid >> 5, lane = tid & 31;
    const int e    = blockIdx.z;
    const int m0   = blockIdx.y * 128, n0 = blockIdx.x * BN;
    const int wm   = (wid >> 1) * 64;
    const int wn   = (wid & 1) * (BN / 2);

    const unsigned sb0 = smem_u32(buf[0]);

    // ---- A sources: pre-split bf16 planes ----
    const __nv_bfloat16 *ah_p, *al_p;
    if (FIRST) {
        int tok = g_indices[e * K_CAP + m0 + tid];
        ah_p = xh + (size_t)tok * H_DIM;
        al_p = xl + (size_t)tok * H_DIM;
    } else {
        size_t r = (size_t)(e * K_CAP + m0 + tid);
        ah_p = hbh + r * F_DIM;
        al_p = hbl + r * F_DIM;
    }
    const unsigned a_d0 = (unsigned)tid * 64u + ((0u ^ ((unsigned)tid & 3u)) * 16u);
    const unsigned a_d1 = (unsigned)tid * 64u + ((1u ^ ((unsigned)tid & 3u)) * 16u);

    // ---- B source (fp32) + store addresses ----
    const float* bsrc;
    unsigned b_st[4];
    if constexpr (FIRST) {
        int brow_g = tid >> 5, bc = tid & 31;
        bsrc = w + (size_t)e * KTOT * NEXP + (size_t)(brow_g * 4) * NEXP + n0 + bc * 4;
#pragma unroll
        for (int j = 0; j < 4; ++j) {
            unsigned brow = (unsigned)(brow_g * 4 + j);
            b_st[j] = brow * BROWB
                    + ((((unsigned)bc >> 1) ^ (brow & 7u)) * 16u) + (bc & 1) * 8u;
        }
    } else {
        int brow = tid >> 3, bu = tid & 7;
        bsrc = w + (size_t)e * KTOT * NEXP + (size_t)brow * NEXP + n0 + bu * 8;
        b_st[0] = (unsigned)brow * BROWB + (((unsigned)bu ^ ((unsigned)brow & 7u)) * 16u);
        b_st[1] = b_st[0] + 8u;
        b_st[2] = b_st[3] = 0;
    }

    float4 pb[4];
    auto ldg_B = [&](int kt) {
        if constexpr (FIRST) {
#pragma unroll
            for (int j = 0; j < 4; ++j)
                pb[j] = *(const float4*)(bsrc + (size_t)(kt * 16 + j) * NEXP);
        } else {
            pb[0] = *(const float4*)(bsrc + (size_t)(kt * 16) * NEXP);
            pb[1] = *(const float4*)(bsrc + (size_t)(kt * 16) * NEXP + 4);
        }
    };
    auto sts_B = [&](int bi) {
        unsigned char* bp = buf[0] + (size_t)bi * STRIDE;
        if constexpr (FIRST) {
#pragma unroll
            for (int j = 0; j < 4; ++j) {
                uint2 hi, lo;
                cvt_split4(pb[j], hi, lo);
                *(uint2*)(bp + BH + b_st[j]) = hi;
                *(uint2*)(bp + BL + b_st[j]) = lo;
            }
        } else {
#pragma unroll
            for (int j = 0; j < 2; ++j) {
                uint2 hi, lo;
                cvt_split4(pb[j], hi, lo);
                *(uint2*)(bp + BH + b_st[j]) = hi;
                *(uint2*)(bp + BL + b_st[j]) = lo;
            }
        }
    };
    auto issue_A = [&](int kt, int bi) {
        unsigned sa = sb0 + (unsigned)bi * STRIDE;
        cp16(sa + AH + a_d0, ah_p + kt * 16);
        cp16(sa + AH + a_d1, ah_p + kt * 16 + 8);
        cp16(sa + AL + a_d0, al_p + kt * 16);
        cp16(sa + AL + a_d1, al_p + kt * 16 + 8);
        asm volatile("cp.async.commit_group;" ::: "memory");
    };

    float acc[4][NT][4];
#pragma unroll
    for (int mt = 0; mt < 4; ++mt)
#pragma unroll
        for (int nt = 0; nt < NT; ++nt)
#pragma unroll
            for (int q = 0; q < 4; ++q) acc[mt][nt][q] = 0.0f;

    auto compute = [&](unsigned base) {
        unsigned ah[4][4], al[4][4];
#pragma unroll
        for (int mt = 0; mt < 4; ++mt) {
            unsigned row = (unsigned)(wm + mt * 16 + (lane & 15));
            unsigned unit = (unsigned)(lane >> 4);
            unsigned off = row * 64u + ((unit ^ (row & 3u)) * 16u);
            ldsm4(ah[mt][0], ah[mt][1], ah[mt][2], ah[mt][3], base + AH + off);
            ldsm4(al[mt][0], al[mt][1], al[mt][2], al[mt][3], base + AL + off);
        }
        unsigned bh[NT][2], bl[NT][2];
#pragma unroll
        for (int p = 0; p < NT / 2; ++p) {
            int g = lane >> 3;
            unsigned krow = (unsigned)((g & 1) * 8 + (lane & 7));
            unsigned unit = (unsigned)((wn >> 3) + 2 * p + (g >> 1));
            unsigned off = krow * BROWB + ((unit ^ (krow & 7u)) * 16u);
            unsigned r0, r1, r2, r3;
            ldsm4t(r0, r1, r2, r3, base + BH + off);
            bh[2 * p][0] = r0;     bh[2 * p][1] = r1;
            bh[2 * p + 1][0] = r2; bh[2 * p + 1][1] = r3;
            ldsm4t(r0, r1, r2, r3, base + BL + off);
            bl[2 * p][0] = r0;     bl[2 * p][1] = r1;
            bl[2 * p + 1][0] = r2; bl[2 * p + 1][1] = r3;
        }
#pragma unroll
        for (int mt = 0; mt < 4; ++mt)
#pragma unroll
            for (int nt = 0; nt < NT; ++nt) {
                mma16816(acc[mt][nt], ah[mt], bh[nt]);
                mma16816(acc[mt][nt], al[mt], bh[nt]);
                mma16816(acc[mt][nt], ah[mt], bl[nt]);
            }
    };

    // ---- pipelined main loop: A async (prev iter), B reg-prefetch ----
    issue_A(0, 0);
    ldg_B(0);
    for (int kt = 0; kt < NCH; ++kt) {
        sts_B(kt & 1);
        asm volatile("cp.async.wait_group 0;" ::: "memory");
        __syncthreads();
        if (kt + 1 < NCH) {
            issue_A(kt + 1, (kt + 1) & 1);
            ldg_B(kt + 1);
        }
        compute(sb0 + (unsigned)(kt & 1) * STRIDE);
    }

    // ---- epilogue ----
#pragma unroll
    for (int mt = 0; mt < 4; ++mt) {
#pragma unroll
        for (int nt = 0; nt < NT; ++nt) {
            int row0 = m0 + wm + mt * 16 + (lane >> 2);
            int cc   = n0 + wn + nt * 8 + 2 * (lane & 3);
#pragma unroll
            for (int hrow = 0; hrow < 2; ++hrow) {
                float v0 = acc[mt][nt][2 * hrow + 0];
                float v1 = acc[mt][nt][2 * hrow + 1];
                if (FIRST) {
                    float s0 = silu_f(v0), s1 = silu_f(v1);
                    __nv_bfloat162 h = __float22bfloat162_rn(make_float2(s0, s1));
                    float2 hf = __bfloat1622float2(h);
                    __nv_bfloat162 l =
                        __float22bfloat162_rn(make_float2(s0 - hf.x, s1 - hf.y));
                    size_t g0 = ((size_t)e * K_CAP + row0 + 8 * hrow) * (size_t)F_DIM + cc;
                    *(unsigned*)(hbh + g0) = *reinterpret_cast<unsigned*>(&h);
                    *(unsigned*)(hbl + g0) = *reinterpret_cast<unsigned*>(&l);
                } else {
                    size_t g0 = ((size_t)e * K_CAP + row0 + 8 * hrow) * (size_t)H_DIM + cc;
                    float2 s;
                    s.x = v0;
                    s.y = v1;
                    *(float2*)(g_eo + g0) = s;
                }
            }
        }
    }
}

// ---------------- deterministic scatter (fixed e-ascending sum order) -------
__global__ void scatter_kernel(float* __restrict__ out) {
    int t = blockIdx.x, tid = threadIdx.x;
    __shared__ int ssl[E_NUM];
    if (tid < E_NUM) ssl[tid] = g_slot[t * E_NUM + tid];
    __syncthreads();
    int j = tid * 4;
    float4 sum = make_float4(0.f, 0.f, 0.f, 0.f);
#pragma unroll
    for (int e = 0; e < E_NUM; ++e) {
        int sl = ssl[e];
        if (sl >= 0) {
            float4 v = *(const float4*)(g_eo + ((size_t)e * K_CAP + sl) * H_DIM + j);
            sum.x += v.x; sum.y += v.y; sum.z += v.z; sum.w += v.w;
        }
    }
    *(float4*)(out + (size_t)t * H_DIM + j) = sum;
}

// ---------------- launch ----------------------------------------------------
extern "C" void kernel_launch(void* const* d_in, const int* in_sizes, int n_in,
                              void* d_out, int out_size) {
    const float* x  = (const float*)d_in[0];   // [4,2048,1024]
    const float* gw = (const float*)d_in[1];   // [1024,8]
    const float* w1 = (const float*)d_in[2];   // [8,1024,4096]
    const float* w2 = (const float*)d_in[3];   // [8,4096,1024]
    float* out = (float*)d_out;
    (void)in_sizes; (void)n_in;

    // loss scalar = 0 exactly (expert_load == k for all experts)
    cudaMemsetAsync(d_out, 0, (size_t)out_size * sizeof(float), 0);

    gate_kernel<<<N_TOK, 256>>>(x, gw);                 // logits + x hi/lo split
    sort_chunk_kernel<<<dim3(8, E_NUM), 1024>>>();      // 64 parallel chunk sorts
    merge8_kernel<<<E_NUM, 1024>>>();                   // exact rank merge

    moe_gemm_kernel<true ><<<dim3(F_DIM / 128, K_CAP / 128, E_NUM), 128>>>(w1);
    moe_gemm_kernel<false><<<dim3(H_DIM / 64,  K_CAP / 128, E_NUM), 128>>>(w2);

    scatter_kernel<<<N_TOK, 256>>>(out);
}

// round 14
// speedup vs baseline: 1.1212x; 1.1212x over previous
#include <cuda_runtime.h>
#include <cuda_bf16.h>

// ---------------- problem constants -----------------------------------------
#define N_TOK 8192
#define H_DIM 1024
#define F_DIM 4096
#define E_NUM 8
#define K_CAP 1280   // int(8192 * 1.25 / 8)

// ---------------- scratch: total ~286.5 MB (< 512 MB failure line) ----------
__device__ unsigned long long g_keys[E_NUM * N_TOK];     // 512 KB
__device__ unsigned long long g_sort[E_NUM * N_TOK];     // 512 KB
__device__ int   g_indices[E_NUM * K_CAP];               // 40 KB
__device__ int   g_slot[N_TOK * E_NUM];                  // 256 KB
__device__ __nv_bfloat16 xh [(size_t)N_TOK * H_DIM];     // 16.8 MB
__device__ __nv_bfloat16 xl [(size_t)N_TOK * H_DIM];     // 16.8 MB
__device__ __nv_bfloat16 hbh[(size_t)E_NUM * K_CAP * F_DIM];  // 83.9 MB
__device__ __nv_bfloat16 hbl[(size_t)E_NUM * K_CAP * F_DIM];  // 83.9 MB
__device__ float g_eo[(size_t)2 * E_NUM * K_CAP * H_DIM];     // 83.9 MB (2 planes)

#define EOP ((size_t)E_NUM * K_CAP * H_DIM)

// ---------------- helpers -----------------------------------------------------
__device__ __forceinline__ unsigned smem_u32(const void* p) {
    unsigned a;
    asm("{ .reg .u64 t; cvta.to.shared.u64 t, %1; cvt.u32.u64 %0, t; }" : "=r"(a) : "l"(p));
    return a;
}
__device__ __forceinline__ void cp16(unsigned dst, const void* src) {
    asm volatile("cp.async.cg.shared.global [%0], [%1], 16;" :: "r"(dst), "l"(src));
}
__device__ __forceinline__ void ldsm4(unsigned& r0, unsigned& r1, unsigned& r2,
                                      unsigned& r3, unsigned addr) {
    asm volatile("ldmatrix.sync.aligned.m8n8.x4.shared.b16 {%0,%1,%2,%3}, [%4];"
                 : "=r"(r0), "=r"(r1), "=r"(r2), "=r"(r3) : "r"(addr));
}
__device__ __forceinline__ void ldsm4t(unsigned& r0, unsigned& r1, unsigned& r2,
                                       unsigned& r3, unsigned addr) {
    asm volatile("ldmatrix.sync.aligned.m8n8.x4.trans.shared.b16 {%0,%1,%2,%3}, [%4];"
                 : "=r"(r0), "=r"(r1), "=r"(r2), "=r"(r3) : "r"(addr));
}
__device__ __forceinline__ void mma16816(float* c, const unsigned* a, const unsigned* b) {
    asm volatile("mma.sync.aligned.m16n8k16.row.col.f32.bf16.bf16.f32 "
                 "{%0,%1,%2,%3}, {%4,%5,%6,%7}, {%8,%9}, {%0,%1,%2,%3};"
                 : "+f"(c[0]), "+f"(c[1]), "+f"(c[2]), "+f"(c[3])
                 : "r"(a[0]), "r"(a[1]), "r"(a[2]), "r"(a[3]), "r"(b[0]), "r"(b[1]));
}
__device__ __forceinline__ void cvt_split4(float4 v, uint2& hi, uint2& lo) {
    __nv_bfloat162 h01 = __float22bfloat162_rn(make_float2(v.x, v.y));
    __nv_bfloat162 h23 = __float22bfloat162_rn(make_float2(v.z, v.w));
    float2 f01 = __bfloat1622float2(h01);
    float2 f23 = __bfloat1622float2(h23);
    __nv_bfloat162 l01 = __float22bfloat162_rn(make_float2(v.x - f01.x, v.y - f01.y));
    __nv_bfloat162 l23 = __float22bfloat162_rn(make_float2(v.z - f23.x, v.w - f23.y));
    hi.x = *reinterpret_cast<unsigned*>(&h01);
    hi.y = *reinterpret_cast<unsigned*>(&h23);
    lo.x = *reinterpret_cast<unsigned*>(&l01);
    lo.y = *reinterpret_cast<unsigned*>(&l23);
}
__device__ __forceinline__ float silu_f(float v) { return v / (1.0f + expf(-v)); }

// ---------------- gating + x hi/lo split (fused; block = one token) ---------
__global__ void gate_kernel(const float* __restrict__ x,
                            const float* __restrict__ gw) {
    int t = blockIdx.x;
    int tid = threadIdx.x;
    float4 v = *(const float4*)(x + (size_t)t * H_DIM + tid * 4);

    uint2 hh, ll;
    cvt_split4(v, hh, ll);
    *(uint2*)(xh + (size_t)t * H_DIM + tid * 4) = hh;
    *(uint2*)(xl + (size_t)t * H_DIM + tid * 4) = ll;

    double acc[E_NUM];
#pragma unroll
    for (int e = 0; e < E_NUM; ++e) acc[e] = 0.0;
    float vv[4] = {v.x, v.y, v.z, v.w};
#pragma unroll
    for (int r = 0; r < 4; ++r) {
        const float* g = gw + (size_t)(tid * 4 + r) * E_NUM;
#pragma unroll
        for (int e = 0; e < E_NUM; ++e) acc[e] += (double)vv[r] * (double)g[e];
    }
#pragma unroll
    for (int e = 0; e < E_NUM; ++e) {
#pragma unroll
        for (int off = 16; off > 0; off >>= 1)
            acc[e] += __shfl_down_sync(0xffffffffu, acc[e], off);
    }
    __shared__ double red[8][E_NUM];
    int warp = tid >> 5, lane = tid & 31;
    if (lane == 0) {
#pragma unroll
        for (int e = 0; e < E_NUM; ++e) red[warp][e] = acc[e];
    }
    __syncthreads();
    if (tid < E_NUM) {
        double s = 0.0;
        for (int w = 0; w < 8; ++w) s += red[w][tid];
        float lf = (float)s;
        unsigned u = __float_as_uint(lf);
        u = (u & 0x80000000u) ? ~u : (u | 0x80000000u);
        unsigned long long key =
            ((unsigned long long)u << 13) | (unsigned)(8191 - t);
        g_keys[tid * N_TOK + t] = key;
        g_slot[t * E_NUM + tid] = -1;
    }
}

// ---------------- chunk sort: 1024 keys per block, descending ---------------
__global__ void sort_chunk_kernel() {
    __shared__ unsigned long long s[1024];
    int e = blockIdx.y, c = blockIdx.x;
    const unsigned long long* keys = g_keys + e * N_TOK + c * 1024;
    s[threadIdx.x] = ~keys[threadIdx.x];   // ascending of ~k = descending of k
    __syncthreads();
    for (int k = 2; k <= 1024; k <<= 1) {
        for (int j = k >> 1; j > 0; j >>= 1) {
            int i = threadIdx.x, l = i ^ j;
            if (l > i) {
                unsigned long long a = s[i], b = s[l];
                bool up = ((i & k) == 0);
                if (up ? (a > b) : (a < b)) { s[i] = b; s[l] = a; }
            }
            __syncthreads();
        }
    }
    g_sort[e * N_TOK + c * 1024 + threadIdx.x] = ~s[threadIdx.x];
}

// ---------------- 8-way rank merge (exact top-K_CAP) ------------------------
__global__ void merge8_kernel() {
    int e = blockIdx.x;
    const unsigned long long* S = g_sort + e * N_TOK;
    for (int idx = threadIdx.x; idx < N_TOK; idx += 1024) {
        int c = idx >> 10, i = idx & 1023;
        unsigned long long v = S[c * 1024 + i];
        int rank = i;
#pragma unroll
        for (int c2 = 0; c2 < 8; ++c2) {
            if (c2 == c) continue;
            const unsigned long long* o = S + c2 * 1024;
            int lo = 0, hi = 1024;
            while (lo < hi) {
                int mid = (lo + hi) >> 1;
                if (o[mid] > v) lo = mid + 1; else hi = mid;
            }
            rank += lo;
        }
        if (rank < K_CAP) {
            int t = 8191 - (int)(v & 0x1FFFull);
            g_indices[e * K_CAP + rank] = t;
            g_slot[t * E_NUM + e] = rank;
        }
    }
}

// ---------------- HMMA GEMM: 128x128 tile, BK=16 ----------------------------
// A (pre-split bf16 planes, cp.async): 128 rows x 16k, 64B rows, swz u^(m&3)
// B (fp32 -> reg CVT -> STS): 16 rows x 128n, 256B rows, swz u^(k&7)
// GEMM2 uses KSPLIT=2 (two g_eo planes summed deterministically in scatter).
template<bool FIRST, int KSPLIT>
__global__ __launch_bounds__(128, 2)
void moe_gemm_kernel(const float* __restrict__ w) {
    constexpr int KTOT = FIRST ? H_DIM : F_DIM;
    constexpr int KLOC = KTOT / KSPLIT;
    constexpr int NEXP = FIRST ? F_DIM : H_DIM;
    constexpr int NCH  = KLOC / 16;
    constexpr unsigned AH = 0, AL = 8192, BH = 16384, BL = 20480;
    constexpr unsigned STRIDE = 24576;

    __shared__ __align__(1024) unsigned char buf[2][STRIDE];   // 48 KB

    const int tid  = threadIdx.x;
    const int wid  = tid >> 5, lane = tid & 31;
    const int e    = blockIdx.z / KSPLIT;
    const int kh   = blockIdx.z % KSPLIT;
    const int m0   = blockIdx.y * 128, n0 = blockIdx.x * 128;
    const int wm   = (wid >> 1) * 64;
    const int wn   = (wid & 1) * 64;

    const unsigned sb0 = smem_u32(buf[0]);

    // ---- A sources: pre-split bf16 planes ----
    const __nv_bfloat16 *ah_p, *al_p;
    if (FIRST) {
        int tok = g_indices[e * K_CAP + m0 + tid];
        ah_p = xh + (size_t)tok * H_DIM + kh * KLOC;
        al_p = xl + (size_t)tok * H_DIM + kh * KLOC;
    } else {
        size_t r = (size_t)(e * K_CAP + m0 + tid);
        ah_p = hbh + r * F_DIM + kh * KLOC;
        al_p = hbl + r * F_DIM + kh * KLOC;
    }
    const unsigned a_d0 = (unsigned)tid * 64u + ((0u ^ ((unsigned)tid & 3u)) * 16u);
    const unsigned a_d1 = (unsigned)tid * 64u + ((1u ^ ((unsigned)tid & 3u)) * 16u);

    // ---- B source (fp32) + store addresses (R10-proven map) ----
    const int brow_g = tid >> 5, bc = tid & 31;
    const float* bsrc = w + (size_t)e * KTOT * NEXP
                        + (size_t)(kh * KLOC + brow_g * 4) * NEXP + n0 + bc * 4;
    unsigned b_st[4];
#pragma unroll
    for (int j = 0; j < 4; ++j) {
        unsigned brow = (unsigned)(brow_g * 4 + j);
        b_st[j] = brow * 256u
                + ((((unsigned)bc >> 1) ^ (brow & 7u)) * 16u) + (bc & 1) * 8u;
    }

    float4 pb[4];
    auto ldg_B = [&](int kt) {
#pragma unroll
        for (int j = 0; j < 4; ++j)
            pb[j] = *(const float4*)(bsrc + (size_t)(kt * 16 + j) * NEXP);
    };
    auto sts_B = [&](int bi) {
        unsigned char* bp = buf[0] + (size_t)bi * STRIDE;
#pragma unroll
        for (int j = 0; j < 4; ++j) {
            uint2 hi, lo;
            cvt_split4(pb[j], hi, lo);
            *(uint2*)(bp + BH + b_st[j]) = hi;
            *(uint2*)(bp + BL + b_st[j]) = lo;
        }
    };
    auto issue_A = [&](int kt, int bi) {
        unsigned sa = sb0 + (unsigned)bi * STRIDE;
        cp16(sa + AH + a_d0, ah_p + kt * 16);
        cp16(sa + AH + a_d1, ah_p + kt * 16 + 8);
        cp16(sa + AL + a_d0, al_p + kt * 16);
        cp16(sa + AL + a_d1, al_p + kt * 16 + 8);
        asm volatile("cp.async.commit_group;" ::: "memory");
    };

    float acc[4][8][4];
#pragma unroll
    for (int mt = 0; mt < 4; ++mt)
#pragma unroll
        for (int nt = 0; nt < 8; ++nt)
#pragma unroll
            for (int q = 0; q < 4; ++q) acc[mt][nt][q] = 0.0f;

    auto compute = [&](unsigned base) {
        unsigned ah[4][4], al[4][4];
#pragma unroll
        for (int mt = 0; mt < 4; ++mt) {
            unsigned row = (unsigned)(wm + mt * 16 + (lane & 15));
            unsigned unit = (unsigned)(lane >> 4);
            unsigned off = row * 64u + ((unit ^ (row & 3u)) * 16u);
            ldsm4(ah[mt][0], ah[mt][1], ah[mt][2], ah[mt][3], base + AH + off);
            ldsm4(al[mt][0], al[mt][1], al[mt][2], al[mt][3], base + AL + off);
        }
        unsigned bh[8][2], bl[8][2];
#pragma unroll
        for (int p = 0; p < 4; ++p) {
            int g = lane >> 3;
            unsigned krow = (unsigned)((g & 1) * 8 + (lane & 7));
            unsigned unit = (unsigned)((wn >> 3) + 2 * p + (g >> 1));
            unsigned off = krow * 256u + ((unit ^ (krow & 7u)) * 16u);
            unsigned r0, r1, r2, r3;
            ldsm4t(r0, r1, r2, r3, base + BH + off);
            bh[2 * p][0] = r0;     bh[2 * p][1] = r1;
            bh[2 * p + 1][0] = r2; bh[2 * p + 1][1] = r3;
            ldsm4t(r0, r1, r2, r3, base + BL + off);
            bl[2 * p][0] = r0;     bl[2 * p][1] = r1;
            bl[2 * p + 1][0] = r2; bl[2 * p + 1][1] = r3;
        }
#pragma unroll
        for (int mt = 0; mt < 4; ++mt)
#pragma unroll
            for (int nt = 0; nt < 8; ++nt) {
                mma16816(acc[mt][nt], ah[mt], bh[nt]);
                mma16816(acc[mt][nt], al[mt], bh[nt]);
                mma16816(acc[mt][nt], ah[mt], bl[nt]);
            }
    };

    // ---- pipelined main loop: A async (prev iter), B reg-prefetch ----
    issue_A(0, 0);
    ldg_B(0);
    for (int kt = 0; kt < NCH; ++kt) {
        sts_B(kt & 1);
        asm volatile("cp.async.wait_group 0;" ::: "memory");
        __syncthreads();
        if (kt + 1 < NCH) {
            issue_A(kt + 1, (kt + 1) & 1);
            ldg_B(kt + 1);
        }
        compute(sb0 + (unsigned)(kt & 1) * STRIDE);
    }

    // ---- epilogue ----
#pragma unroll
    for (int mt = 0; mt < 4; ++mt) {
#pragma unroll
        for (int nt = 0; nt < 8; ++nt) {
            int row0 = m0 + wm + mt * 16 + (lane >> 2);
            int cc   = n0 + wn + nt * 8 + 2 * (lane & 3);
#pragma unroll
            for (int hrow = 0; hrow < 2; ++hrow) {
                float v0 = acc[mt][nt][2 * hrow + 0];
                float v1 = acc[mt][nt][2 * hrow + 1];
                if (FIRST) {
                    float s0 = silu_f(v0), s1 = silu_f(v1);
                    __nv_bfloat162 h = __float22bfloat162_rn(make_float2(s0, s1));
                    float2 hf = __bfloat1622float2(h);
                    __nv_bfloat162 l =
                        __float22bfloat162_rn(make_float2(s0 - hf.x, s1 - hf.y));
                    size_t g0 = ((size_t)e * K_CAP + row0 + 8 * hrow) * (size_t)F_DIM + cc;
                    *(unsigned*)(hbh + g0) = *reinterpret_cast<unsigned*>(&h);
                    *(unsigned*)(hbl + g0) = *reinterpret_cast<unsigned*>(&l);
                } else {
                    size_t g0 = kh * EOP
                              + ((size_t)e * K_CAP + row0 + 8 * hrow) * (size_t)H_DIM + cc;
                    float2 s;
                    s.x = v0;
                    s.y = v1;
                    *(float2*)(g_eo + g0) = s;
                }
            }
        }
    }
}

// ---------------- deterministic scatter (sums both split-K planes) ----------
__global__ void scatter_kernel(float* __restrict__ out) {
    int t = blockIdx.x, tid = threadIdx.x;
    __shared__ int ssl[E_NUM];
    if (tid < E_NUM) ssl[tid] = g_slot[t * E_NUM + tid];
    __syncthreads();
    int j = tid * 4;
    float4 sum = make_float4(0.f, 0.f, 0.f, 0.f);
#pragma unroll
    for (int e = 0; e < E_NUM; ++e) {
        int sl = ssl[e];
        if (sl >= 0) {
            size_t base = ((size_t)e * K_CAP + sl) * H_DIM + j;
            float4 v0 = *(const float4*)(g_eo + base);
            float4 v1 = *(const float4*)(g_eo + EOP + base);
            sum.x += v0.x + v1.x; sum.y += v0.y + v1.y;
            sum.z += v0.z + v1.z; sum.w += v0.w + v1.w;
        }
    }
    *(float4*)(out + (size_t)t * H_DIM + j) = sum;
}

// ---------------- launch ----------------------------------------------------
extern "C" void kernel_launch(void* const* d_in, const int* in_sizes, int n_in,
                              void* d_out, int out_size) {
    const float* x  = (const float*)d_in[0];   // [4,2048,1024]
    const float* gw = (const float*)d_in[1];   // [1024,8]
    const float* w1 = (const float*)d_in[2];   // [8,1024,4096]
    const float* w2 = (const float*)d_in[3];   // [8,4096,1024]
    float* out = (float*)d_out;
    (void)in_sizes; (void)n_in;

    // loss scalar = 0 exactly (expert_load == k for all experts)
    cudaMemsetAsync(d_out, 0, (size_t)out_size * sizeof(float), 0);

    gate_kernel<<<N_TOK, 256>>>(x, gw);                 // logits + x hi/lo split
    sort_chunk_kernel<<<dim3(8, E_NUM), 1024>>>();      // 64 parallel chunk sorts
    merge8_kernel<<<E_NUM, 1024>>>();                   // exact rank merge

    moe_gemm_kernel<true, 1><<<dim3(F_DIM / 128, K_CAP / 128, E_NUM), 128>>>(w1);
    moe_gemm_kernel<false, 2><<<dim3(H_DIM / 128, K_CAP / 128, E_NUM * 2), 128>>>(w2);

    scatter_kernel<<<N_TOK, 256>>>(out);
}

// round 16
// speedup vs baseline: 1.1896x; 1.0611x over previous
#include <cuda_runtime.h>
#include <cuda_bf16.h>

// ---------------- problem constants -----------------------------------------
#define N_TOK 8192
#define H_DIM 1024
#define F_DIM 4096
#define E_NUM 8
#define K_CAP 1280   // int(8192 * 1.25 / 8)

// ---------------- scratch: total ~253.0 MB (< 512 MB failure line) ----------
__device__ unsigned long long g_keys[E_NUM * N_TOK];     // 512 KB
__device__ unsigned long long g_sort[E_NUM * N_TOK];     // 512 KB
__device__ int   g_indices[E_NUM * K_CAP];               // 40 KB
__device__ int   g_slot[N_TOK * E_NUM];                  // 256 KB
__device__ float g_h [(size_t)E_NUM * K_CAP * F_DIM];    // 167.8 MB fp32 interm.
__device__ float g_eo[(size_t)2 * E_NUM * K_CAP * H_DIM];// 83.9 MB, 2 split-K planes

#define EOP ((size_t)E_NUM * K_CAP * H_DIM)

// ---------------- helpers -----------------------------------------------------
__device__ __forceinline__ unsigned smem_u32(const void* p) {
    unsigned a;
    asm("{ .reg .u64 t; cvta.to.shared.u64 t, %1; cvt.u32.u64 %0, t; }" : "=r"(a) : "l"(p));
    return a;
}
__device__ __forceinline__ void ldsm4(unsigned& r0, unsigned& r1, unsigned& r2,
                                      unsigned& r3, unsigned addr) {
    asm volatile("ldmatrix.sync.aligned.m8n8.x4.shared.b16 {%0,%1,%2,%3}, [%4];"
                 : "=r"(r0), "=r"(r1), "=r"(r2), "=r"(r3) : "r"(addr));
}
__device__ __forceinline__ void ldsm4t(unsigned& r0, unsigned& r1, unsigned& r2,
                                       unsigned& r3, unsigned addr) {
    asm volatile("ldmatrix.sync.aligned.m8n8.x4.trans.shared.b16 {%0,%1,%2,%3}, [%4];"
                 : "=r"(r0), "=r"(r1), "=r"(r2), "=r"(r3) : "r"(addr));
}
__device__ __forceinline__ void mma16816(float* c, const unsigned* a, const unsigned* b) {
    asm volatile("mma.sync.aligned.m16n8k16.row.col.f32.bf16.bf16.f32 "
                 "{%0,%1,%2,%3}, {%4,%5,%6,%7}, {%8,%9}, {%0,%1,%2,%3};"
                 : "+f"(c[0]), "+f"(c[1]), "+f"(c[2]), "+f"(c[3])
                 : "r"(a[0]), "r"(a[1]), "r"(a[2]), "r"(a[3]), "r"(b[0]), "r"(b[1]));
}
// split float4 into packed hi (2x u32) and lo (2x u32), pairwise cvt
__device__ __forceinline__ void cvt_split4(float4 v, uint2& hi, uint2& lo) {
    __nv_bfloat162 h01 = __float22bfloat162_rn(make_float2(v.x, v.y));
    __nv_bfloat162 h23 = __float22bfloat162_rn(make_float2(v.z, v.w));
    float2 f01 = __bfloat1622float2(h01);
    float2 f23 = __bfloat1622float2(h23);
    __nv_bfloat162 l01 = __float22bfloat162_rn(make_float2(v.x - f01.x, v.y - f01.y));
    __nv_bfloat162 l23 = __float22bfloat162_rn(make_float2(v.z - f23.x, v.w - f23.y));
    hi.x = *reinterpret_cast<unsigned*>(&h01);
    hi.y = *reinterpret_cast<unsigned*>(&h23);
    lo.x = *reinterpret_cast<unsigned*>(&l01);
    lo.y = *reinterpret_cast<unsigned*>(&l23);
}
__device__ __forceinline__ float silu_f(float v) { return v / (1.0f + expf(-v)); }

// ---------------- gating: fp64-accurate logits -> sortable 64-bit keys ------
__global__ void gate_kernel(const float* __restrict__ x,
                            const float* __restrict__ gw) {
    int t = blockIdx.x;
    int tid = threadIdx.x;
    double acc[E_NUM];
#pragma unroll
    for (int e = 0; e < E_NUM; ++e) acc[e] = 0.0;
    const float* xr = x + (size_t)t * H_DIM;
    for (int h = tid; h < H_DIM; h += 256) {
        double xv = (double)xr[h];
        const float* g = gw + h * E_NUM;
#pragma unroll
        for (int e = 0; e < E_NUM; ++e) acc[e] += xv * (double)g[e];
    }
#pragma unroll
    for (int e = 0; e < E_NUM; ++e) {
#pragma unroll
        for (int off = 16; off > 0; off >>= 1)
            acc[e] += __shfl_down_sync(0xffffffffu, acc[e], off);
    }
    __shared__ double red[8][E_NUM];
    int warp = tid >> 5, lane = tid & 31;
    if (lane == 0) {
#pragma unroll
        for (int e = 0; e < E_NUM; ++e) red[warp][e] = acc[e];
    }
    __syncthreads();
    if (tid < E_NUM) {
        double s = 0.0;
        for (int w = 0; w < 8; ++w) s += red[w][tid];
        float lf = (float)s;
        unsigned u = __float_as_uint(lf);
        u = (u & 0x80000000u) ? ~u : (u | 0x80000000u);
        unsigned long long key =
            ((unsigned long long)u << 13) | (unsigned)(8191 - t);
        g_keys[tid * N_TOK + t] = key;
        g_slot[t * E_NUM + tid] = -1;
    }
}

// ---------------- chunk sort: 1024 keys per block, descending ---------------
__global__ void sort_chunk_kernel() {
    __shared__ unsigned long long s[1024];
    int e = blockIdx.y, c = blockIdx.x;
    const unsigned long long* keys = g_keys + e * N_TOK + c * 1024;
    s[threadIdx.x] = ~keys[threadIdx.x];   // ascending of ~k = descending of k
    __syncthreads();
    for (int k = 2; k <= 1024; k <<= 1) {
        for (int j = k >> 1; j > 0; j >>= 1) {
            int i = threadIdx.x, l = i ^ j;
            if (l > i) {
                unsigned long long a = s[i], b = s[l];
                bool up = ((i & k) == 0);
                if (up ? (a > b) : (a < b)) { s[i] = b; s[l] = a; }
            }
            __syncthreads();
        }
    }
    g_sort[e * N_TOK + c * 1024 + threadIdx.x] = ~s[threadIdx.x];
}

// ---------------- 8-way rank merge (exact top-K_CAP, MLP=7 searches) --------
// 11 steps: interval length 1024 needs ceil(log2(1024))+1 = 11 halvings to
// reach lo==hi (10 steps can leave length-1 intervals -> off-by-one ranks).
__global__ void merge8_kernel() {
    int e = blockIdx.y, c = blockIdx.x, i = threadIdx.x;
    const unsigned long long* S = g_sort + e * N_TOK;
    unsigned long long v = S[c * 1024 + i];
    int lo[8], hi[8];
#pragma unroll
    for (int c2 = 0; c2 < 8; ++c2) { lo[c2] = 0; hi[c2] = 1024; }
    lo[c] = hi[c] = 0;   // skip own chunk
    for (int s = 0; s < 11; ++s) {
#pragma unroll
        for (int c2 = 0; c2 < 8; ++c2) {
            if (lo[c2] < hi[c2]) {
                int mid = (lo[c2] + hi[c2]) >> 1;
                if (S[c2 * 1024 + mid] > v) lo[c2] = mid + 1; else hi[c2] = mid;
            }
        }
    }
    int rank = i;
#pragma unroll
    for (int c2 = 0; c2 < 8; ++c2) rank += lo[c2];
    if (rank < K_CAP) {
        int t = 8191 - (int)(v & 0x1FFFull);
        g_indices[e * K_CAP + rank] = t;
        g_slot[t * E_NUM + e] = rank;
    }
}

// ---------------- HMMA GEMM: 128x128 tile, BK=16, reg-prefetch pipeline -----
// (verbatim from the 1843us-proven R10 kernel)
// Per buffer (24 KB): Ah[128x64B] swz u^(m&3) | Al | Bh[16x256B] swz u^(k&7) | Bl
// Loop: STS(regs->buf[kt&1]) ; sync ; LDG(kt+1->regs) ; compute(buf[kt&1])
template<bool FIRST, int KSPLIT>
__global__ __launch_bounds__(128, 2)
void moe_gemm_kernel(const float* __restrict__ x,
                     const float* __restrict__ w) {
    constexpr int KTOT = FIRST ? H_DIM : F_DIM;
    constexpr int KLOC = KTOT / KSPLIT;
    constexpr int NEXP = FIRST ? F_DIM : H_DIM;
    constexpr int NCH  = KLOC / 16;
    constexpr unsigned AH = 0, AL = 8192, BH = 16384, BL = 20480;

    __shared__ __align__(1024) unsigned char buf[2][24576];   // 48 KB exactly

    const int tid  = threadIdx.x;
    const int wid  = tid >> 5, lane = tid & 31;
    const int e    = blockIdx.z / KSPLIT;
    const int kh   = blockIdx.z % KSPLIT;
    const int m0   = blockIdx.y * 128, n0 = blockIdx.x * 128;
    const int wm   = (wid >> 1) * 64;
    const int wn   = (wid & 1) * 64;

    const unsigned sb0 = smem_u32(buf[0]);

    // ---- token ids via smem overlay on buf[0] (GEMM1 only) ----
    int* stok = (int*)buf[0];
    if (FIRST) stok[tid] = g_indices[e * K_CAP + m0 + tid];
    __syncthreads();

    // ---- staging maps ----
    const int af     = tid & 3;    // A: float4 unit within 16-k row
    const int arow_g = tid >> 2;   // A: row = j*32 + arow_g  (j = 0..3)
    const int bc     = tid & 31;   // B: col block (4 floats)
    const int brow_g = tid >> 5;   // B: row = brow_g*4 + j   (j = 0..3)

    const float* abase[4];
#pragma unroll
    for (int j = 0; j < 4; ++j) {
        int row = j * 32 + arow_g;
        if (FIRST)
            abase[j] = x + (size_t)stok[row] * H_DIM + kh * KLOC + af * 4;
        else
            abase[j] = g_h + ((size_t)e * K_CAP + m0 + row) * F_DIM + kh * KLOC + af * 4;
    }
    const float* bbase = w + (size_t)e * KTOT * NEXP
                         + (size_t)(kh * KLOC + brow_g * 4) * NEXP + n0 + bc * 4;
    __syncthreads();   // all stok reads done before buf[0] is overwritten

    float acc[4][8][4];
#pragma unroll
    for (int mt = 0; mt < 4; ++mt)
#pragma unroll
        for (int nt = 0; nt < 8; ++nt)
#pragma unroll
            for (int q = 0; q < 4; ++q) acc[mt][nt][q] = 0.0f;

    // precomputed store addresses (buffer-relative, loop-invariant)
    unsigned a_st[4], b_st[4];
#pragma unroll
    for (int j = 0; j < 4; ++j) {
        unsigned srow = (unsigned)(j * 32 + arow_g);
        a_st[j] = srow * 64u
                + ((((unsigned)af >> 1) ^ (srow & 3u)) * 16u) + (af & 1) * 8u;
        unsigned brow = (unsigned)(brow_g * 4 + j);
        b_st[j] = brow * 256u
                + ((((unsigned)bc >> 1) ^ (brow & 7u)) * 16u) + (bc & 1) * 8u;
    }

    // ---- pipeline pieces ----
    float4 pa[4], pb[4];   // prefetch registers (32 regs)

    auto ldg_chunk = [&](int kt) {
#pragma unroll
        for (int j = 0; j < 4; ++j)
            pa[j] = *(const float4*)(abase[j] + kt * 16);
#pragma unroll
        for (int j = 0; j < 4; ++j)
            pb[j] = *(const float4*)(bbase + (size_t)(kt * 16 + j) * NEXP);
    };

    auto sts_chunk = [&](int bi) {
        unsigned char* bp = buf[0] + (size_t)bi * 24576;
#pragma unroll
        for (int j = 0; j < 4; ++j) {
            uint2 hi, lo;
            cvt_split4(pa[j], hi, lo);
            *(uint2*)(bp + AH + a_st[j]) = hi;
            *(uint2*)(bp + AL + a_st[j]) = lo;
        }
#pragma unroll
        for (int j = 0; j < 4; ++j) {
            uint2 hi, lo;
            cvt_split4(pb[j], hi, lo);
            *(uint2*)(bp + BH + b_st[j]) = hi;
            *(uint2*)(bp + BL + b_st[j]) = lo;
        }
    };

    auto compute = [&](unsigned base) {
        unsigned ah[4][4], al[4][4];
#pragma unroll
        for (int mt = 0; mt < 4; ++mt) {
            unsigned row = (unsigned)(wm + mt * 16 + (lane & 15));
            unsigned unit = (unsigned)(lane >> 4);
            unsigned off = row * 64u + ((unit ^ (row & 3u)) * 16u);
            ldsm4(ah[mt][0], ah[mt][1], ah[mt][2], ah[mt][3], base + AH + off);
            ldsm4(al[mt][0], al[mt][1], al[mt][2], al[mt][3], base + AL + off);
        }
        unsigned bh[8][2], bl[8][2];
#pragma unroll
        for (int p = 0; p < 4; ++p) {
            int g = lane >> 3;
            unsigned krow = (unsigned)((g & 1) * 8 + (lane & 7));
            unsigned unit = (unsigned)((wn >> 3) + 2 * p + (g >> 1));
            unsigned off = krow * 256u + ((unit ^ (krow & 7u)) * 16u);
            unsigned r0, r1, r2, r3;
            ldsm4t(r0, r1, r2, r3, base + BH + off);
            bh[2 * p][0] = r0;     bh[2 * p][1] = r1;
            bh[2 * p + 1][0] = r2; bh[2 * p + 1][1] = r3;
            ldsm4t(r0, r1, r2, r3, base + BL + off);
            bl[2 * p][0] = r0;     bl[2 * p][1] = r1;
            bl[2 * p + 1][0] = r2; bl[2 * p + 1][1] = r3;
        }
#pragma unroll
        for (int mt = 0; mt < 4; ++mt)
#pragma unroll
            for (int nt = 0; nt < 8; ++nt) {
                mma16816(acc[mt][nt], ah[mt], bh[nt]);
                mma16816(acc[mt][nt], al[mt], bh[nt]);
                mma16816(acc[mt][nt], ah[mt], bl[nt]);
            }
    };

    // ---- register-prefetch main loop ----
    ldg_chunk(0);
    for (int kt = 0; kt < NCH; ++kt) {
        sts_chunk(kt & 1);                 // regs -> smem (cheap, exposed)
        __syncthreads();
        if (kt + 1 < NCH) ldg_chunk(kt + 1);   // long-latency, hidden below
        compute(sb0 + (unsigned)(kt & 1) * 24576u);
    }

    // ---- epilogue ----
#pragma unroll
    for (int mt = 0; mt < 4; ++mt) {
#pragma unroll
        for (int nt = 0; nt < 8; ++nt) {
            int row0 = m0 + wm + mt * 16 + (lane >> 2);
            int cc   = n0 + wn + nt * 8 + 2 * (lane & 3);
#pragma unroll
            for (int hrow = 0; hrow < 2; ++hrow) {
                float v0 = acc[mt][nt][2 * hrow + 0];
                float v1 = acc[mt][nt][2 * hrow + 1];
                if (FIRST) {
                    size_t g0 = ((size_t)e * K_CAP + row0 + 8 * hrow) * (size_t)F_DIM + cc;
                    float2 s;
                    s.x = silu_f(v0);
                    s.y = silu_f(v1);
                    *(float2*)(g_h + g0) = s;
                } else {
                    size_t g0 = kh * EOP
                              + ((size_t)e * K_CAP + row0 + 8 * hrow) * (size_t)H_DIM + cc;
                    float2 s;
                    s.x = v0;
                    s.y = v1;
                    *(float2*)(g_eo + g0) = s;
                }
            }
        }
    }
}

// ---------------- deterministic scatter (sums both split-K planes) ----------
__global__ void scatter_kernel(float* __restrict__ out) {
    int t = blockIdx.x, tid = threadIdx.x;
    __shared__ int ssl[E_NUM];
    if (tid < E_NUM) ssl[tid] = g_slot[t * E_NUM + tid];
    __syncthreads();
    int j = tid * 4;
    float4 sum = make_float4(0.f, 0.f, 0.f, 0.f);
#pragma unroll
    for (int e = 0; e < E_NUM; ++e) {
        int sl = ssl[e];
        if (sl >= 0) {
            size_t base = ((size_t)e * K_CAP + sl) * H_DIM + j;
            float4 v0 = *(const float4*)(g_eo + base);
            float4 v1 = *(const float4*)(g_eo + EOP + base);
            sum.x += v0.x + v1.x; sum.y += v0.y + v1.y;
            sum.z += v0.z + v1.z; sum.w += v0.w + v1.w;
        }
    }
    *(float4*)(out + (size_t)t * H_DIM + j) = sum;
}

// ---------------- launch ----------------------------------------------------
extern "C" void kernel_launch(void* const* d_in, const int* in_sizes, int n_in,
                              void* d_out, int out_size) {
    const float* x  = (const float*)d_in[0];   // [4,2048,1024]
    const float* gw = (const float*)d_in[1];   // [1024,8]
    const float* w1 = (const float*)d_in[2];   // [8,1024,4096]
    const float* w2 = (const float*)d_in[3];   // [8,4096,1024]
    float* out = (float*)d_out;
    (void)in_sizes; (void)n_in;

    // loss scalar = 0 exactly (expert_load == k for all experts)
    cudaMemsetAsync(d_out, 0, (size_t)out_size * sizeof(float), 0);

    gate_kernel<<<N_TOK, 256>>>(x, gw);
    sort_chunk_kernel<<<dim3(8, E_NUM), 1024>>>();   // 64 parallel chunk sorts
    merge8_kernel<<<dim3(8, E_NUM), 1024>>>();       // 64-CTA exact rank merge

    moe_gemm_kernel<true, 1><<<dim3(F_DIM / 128, K_CAP / 128, E_NUM), 128>>>(x, w1);
    moe_gemm_kernel<false, 2><<<dim3(H_DIM / 128, K_CAP / 128, E_NUM * 2), 128>>>(nullptr, w2);

    scatter_kernel<<<N_TOK, 256>>>(out);
}